// round 10
// baseline (speedup 1.0000x reference)
#include <cuda_runtime.h>
#include <cstdint>

#define IN_DIM 1433
#define HID 16
#define OUTD 7
#define MAXN 200000
#define MAXE 6400000
#define MAXNB 256

// gemm1 mma.sync tiling
#define KSTEPS_FULL 89           // 89*16 = 1424 (all k in-bounds)
#define KP 1448                  // smem pitch (bf16) -> 724 words, 724%32=20 (conflict-free)
#define KPW (KP / 2)
#define SMEM_BHALF (16 * KP * 2)
#define SMEM_B_BYTES (2 * SMEM_BHALF)

// Scratch (__device__ globals; allocations are forbidden)
__device__ float g_xw1[(size_t)MAXN * HID];
__device__ float g_h[(size_t)MAXN * HID];
__device__ float g_g[(size_t)MAXN * 8];
__device__ int2  g_csr[(size_t)MAXE];
__device__ int   g_rowcnt[MAXN];
__device__ int   g_rowfill[MAXN];
__device__ int   g_rowptr[MAXN + 1];
__device__ int   g_blocksum[MAXNB];
__device__ int   g_blockoff[MAXNB];
__device__ int   g_idx64;

// ---------------------------------------------------------------------------
__device__ __forceinline__ void split2(float x0, float x1, uint32_t& hi, uint32_t& lo)
{
    uint32_t u0 = __float_as_uint(x0) & 0xFFFF0000u;
    uint32_t u1 = __float_as_uint(x1) & 0xFFFF0000u;
    hi = __byte_perm(u0, u1, 0x7632);
    float l0 = x0 - __uint_as_float(u0);
    float l1 = x1 - __uint_as_float(u1);
    asm("cvt.rn.bf16x2.f32 %0, %1, %2;" : "=r"(lo) : "f"(l1), "f"(l0));
}

__device__ __forceinline__ void mma16816(float& d0, float& d1, float& d2, float& d3,
                                         uint32_t a0, uint32_t a1, uint32_t a2, uint32_t a3,
                                         uint32_t b0, uint32_t b1)
{
    asm volatile(
        "mma.sync.aligned.m16n8k16.row.col.f32.bf16.bf16.f32 "
        "{%0,%1,%2,%3}, {%4,%5,%6,%7}, {%8,%9}, {%0,%1,%2,%3};"
        : "+f"(d0), "+f"(d1), "+f"(d2), "+f"(d3)
        : "r"(a0), "r"(a1), "r"(a2), "r"(a3), "r"(b0), "r"(b1));
}

// ---------------------------------------------------------------------------
__global__ void detect_idx_kernel(const unsigned int* __restrict__ adj_words, int n_edges)
{
    int i = threadIdx.x;
    int samples = n_edges < 1024 ? n_edges : 1024;
    int ok = 1;
    if (i < samples) ok = (adj_words[2 * i + 1] == 0u) ? 1 : 0;
    int all = __syncthreads_and(ok);
    if (i == 0) g_idx64 = all;
}

__device__ __forceinline__ int load_row(const void* adj, int e, int is64) {
    return is64 ? (int)__ldg((const long long*)adj + e)
                : __ldg((const int*)adj + e);
}
__device__ __forceinline__ int load_col(const void* adj, int e, int n_edges, int is64) {
    return is64 ? (int)__ldg((const long long*)adj + (size_t)n_edges + e)
                : __ldg((const int*)adj + (size_t)n_edges + e);
}

// ---------------------------------------------------------------------------
__global__ void zero_counts_kernel(int n)
{
    int i = blockIdx.x * blockDim.x + threadIdx.x;
    if (i < n) { g_rowcnt[i] = 0; g_rowfill[i] = 0; }
}

__global__ __launch_bounds__(256) void histogram_kernel(
    const void* __restrict__ adj, int n_edges)
{
    int e = blockIdx.x * blockDim.x + threadIdx.x;
    if (e >= n_edges) return;
    int r = load_row(adj, e, g_idx64);
    atomicAdd(&g_rowcnt[r], 1);
}

__device__ __forceinline__ int block_excl_scan(int v, int* warp_sums, int nwarps)
{
    const int lane = threadIdx.x & 31, w = threadIdx.x >> 5;
    int x = v;
    #pragma unroll
    for (int off = 1; off < 32; off <<= 1) {
        int y = __shfl_up_sync(0xffffffffu, x, off);
        if (lane >= off) x += y;
    }
    if (lane == 31) warp_sums[w] = x;
    __syncthreads();
    if (w == 0) {
        int s = (lane < nwarps) ? warp_sums[lane] : 0;
        #pragma unroll
        for (int off = 1; off < 32; off <<= 1) {
            int y = __shfl_up_sync(0xffffffffu, s, off);
            if (lane >= off) s += y;
        }
        if (lane < nwarps) warp_sums[lane] = s;
    }
    __syncthreads();
    int base = (w > 0) ? warp_sums[w - 1] : 0;
    return base + x - v;
}

__global__ __launch_bounds__(1024) void scan1_kernel(int n)
{
    __shared__ int ws[32];
    int i = blockIdx.x * 1024 + threadIdx.x;
    int v = (i < n) ? g_rowcnt[i] : 0;
    int ex = block_excl_scan(v, ws, 32);
    if (threadIdx.x == 1023) g_blocksum[blockIdx.x] = ex + v;
}

__global__ __launch_bounds__(256) void scan2_kernel(int nb)
{
    __shared__ int ws[32];
    int i = threadIdx.x;
    int v = (i < nb) ? g_blocksum[i] : 0;
    int ex = block_excl_scan(v, ws, 8);
    if (i < nb) g_blockoff[i] = ex;
}

__global__ __launch_bounds__(1024) void scan3_kernel(int n)
{
    __shared__ int ws[32];
    int i = blockIdx.x * 1024 + threadIdx.x;
    int v = (i < n) ? g_rowcnt[i] : 0;
    int ex = block_excl_scan(v, ws, 32);
    int base = g_blockoff[blockIdx.x];
    if (i < n)      g_rowptr[i] = base + ex;
    if (i == n - 1) g_rowptr[n] = base + ex + v;
}

__global__ __launch_bounds__(256) void scatter_kernel(
    const void* __restrict__ adj, const float* __restrict__ vals, int n_edges)
{
    int e = blockIdx.x * blockDim.x + threadIdx.x;
    if (e >= n_edges) return;
    const int is64 = g_idx64;
    int r = load_row(adj, e, is64);
    int c = load_col(adj, e, n_edges, is64);
    float v = __ldg(vals + e);
    int pos = g_rowptr[r] + atomicAdd(&g_rowfill[r], 1);
    g_csr[pos] = make_int2(c, __float_as_int(v));
}

// ---------------------------------------------------------------------------
// GEMM1 via mma.sync bf16 split (hh + hl + lh) with 1-deep LDG prefetch.
__global__ __launch_bounds__(512, 2) void gemm1_mma_kernel(
    const float* __restrict__ feature,
    const float* __restrict__ W1,
    int n_nodes, int ntiles256)
{
    extern __shared__ char smem[];
    uint32_t* shi = (uint32_t*)smem;
    uint32_t* slo = (uint32_t*)(smem + SMEM_BHALF);

    const int tid  = threadIdx.x;
    const int warp = tid >> 5;
    const int lane = tid & 31;
    const int g    = lane >> 2;
    const int q2   = (lane & 3) * 2;

    // stage W1^T split (zero-padded to KP)
    for (int idx = tid; idx < 16 * KPW; idx += 512) {
        int n  = idx / KPW;
        int kp = idx - n * KPW;
        int k  = kp * 2;
        float w0 = (k     < IN_DIM) ? __ldg(W1 + (size_t)k       * HID + n) : 0.0f;
        float w1 = (k + 1 < IN_DIM) ? __ldg(W1 + (size_t)(k + 1) * HID + n) : 0.0f;
        uint32_t hi, lo;
        split2(w0, w1, hi, lo);
        shi[n * KPW + kp] = hi;
        slo[n * KPW + kp] = lo;
    }
    __syncthreads();

    const int bw0 = g * KPW + (lane & 3);
    const int bw1 = (8 + g) * KPW + (lane & 3);

    for (int t = blockIdx.x; t < ntiles256; t += gridDim.x) {
        const int row0 = t * 256 + warp * 16;
        const int rg0  = row0 + g;
        const int rg1  = rg0 + 8;
        const bool full = (row0 + 15 < n_nodes);

        float d[2][4];
        #pragma unroll
        for (int h = 0; h < 2; h++)
            #pragma unroll
            for (int j = 0; j < 4; j++) d[h][j] = 0.0f;

        const float* p0 = feature + (size_t)rg0 * IN_DIM + q2;
        const float* p1 = feature + (size_t)rg1 * IN_DIM + q2;

        if (full) {
            // preload k-step 0
            float fc[8];
            fc[0] = __ldg(p0);     fc[1] = __ldg(p0 + 1);
            fc[2] = __ldg(p0 + 8); fc[3] = __ldg(p0 + 9);
            fc[4] = __ldg(p1);     fc[5] = __ldg(p1 + 1);
            fc[6] = __ldg(p1 + 8); fc[7] = __ldg(p1 + 9);

            #pragma unroll 1
            for (int s = 0; s < KSTEPS_FULL; s++) {
                // prefetch next k-step's 8 loads before consuming fc
                float fx[8];
                if (s + 1 < KSTEPS_FULL) {
                    const int kn = (s + 1) * 16;
                    fx[0] = __ldg(p0 + kn);     fx[1] = __ldg(p0 + kn + 1);
                    fx[2] = __ldg(p0 + kn + 8); fx[3] = __ldg(p0 + kn + 9);
                    fx[4] = __ldg(p1 + kn);     fx[5] = __ldg(p1 + kn + 1);
                    fx[6] = __ldg(p1 + kn + 8); fx[7] = __ldg(p1 + kn + 9);
                }

                uint32_t a0h, a0l, a1h, a1l, a2h, a2l, a3h, a3l;
                split2(fc[0], fc[1], a0h, a0l);
                split2(fc[2], fc[3], a2h, a2l);
                split2(fc[4], fc[5], a1h, a1l);
                split2(fc[6], fc[7], a3h, a3l);

                const int kw = s * 8;   // (s*16) >> 1
                #pragma unroll
                for (int h = 0; h < 2; h++) {
                    const int base = (h ? bw1 : bw0) + kw;
                    const uint32_t b0h = shi[base], b1h = shi[base + 4];
                    const uint32_t b0l = slo[base], b1l = slo[base + 4];
                    mma16816(d[h][0], d[h][1], d[h][2], d[h][3],
                             a0h, a1h, a2h, a3h, b0h, b1h);
                    mma16816(d[h][0], d[h][1], d[h][2], d[h][3],
                             a0h, a1h, a2h, a3h, b0l, b1l);
                    mma16816(d[h][0], d[h][1], d[h][2], d[h][3],
                             a0l, a1l, a2l, a3l, b0h, b1h);
                }

                if (s + 1 < KSTEPS_FULL) {
                    #pragma unroll
                    for (int i = 0; i < 8; i++) fc[i] = fx[i];
                }
            }
            {   // k tail: k0 = 1424 (cols 1424..1439, valid < 1433)
                const int k0 = KSTEPS_FULL * 16;
                float f00 = (k0 + q2     < IN_DIM) ? __ldg(p0 + k0)     : 0.0f;
                float f01 = (k0 + q2 + 1 < IN_DIM) ? __ldg(p0 + k0 + 1) : 0.0f;
                float f02 = (k0 + q2 + 8 < IN_DIM) ? __ldg(p0 + k0 + 8) : 0.0f;
                float f03 = (k0 + q2 + 9 < IN_DIM) ? __ldg(p0 + k0 + 9) : 0.0f;
                float f10 = (k0 + q2     < IN_DIM) ? __ldg(p1 + k0)     : 0.0f;
                float f11 = (k0 + q2 + 1 < IN_DIM) ? __ldg(p1 + k0 + 1) : 0.0f;
                float f12 = (k0 + q2 + 8 < IN_DIM) ? __ldg(p1 + k0 + 8) : 0.0f;
                float f13 = (k0 + q2 + 9 < IN_DIM) ? __ldg(p1 + k0 + 9) : 0.0f;
                uint32_t a0h, a0l, a1h, a1l, a2h, a2l, a3h, a3l;
                split2(f00, f01, a0h, a0l);
                split2(f02, f03, a2h, a2l);
                split2(f10, f11, a1h, a1l);
                split2(f12, f13, a3h, a3l);
                const int kw = k0 >> 1;
                #pragma unroll
                for (int h = 0; h < 2; h++) {
                    const int base = (h ? bw1 : bw0) + kw;
                    const uint32_t b0h = shi[base], b1h = shi[base + 4];
                    const uint32_t b0l = slo[base], b1l = slo[base + 4];
                    mma16816(d[h][0], d[h][1], d[h][2], d[h][3],
                             a0h, a1h, a2h, a3h, b0h, b1h);
                    mma16816(d[h][0], d[h][1], d[h][2], d[h][3],
                             a0h, a1h, a2h, a3h, b0l, b1l);
                    mma16816(d[h][0], d[h][1], d[h][2], d[h][3],
                             a0l, a1l, a2l, a3l, b0h, b1h);
                }
            }
        } else {
            const bool r0ok = (rg0 < n_nodes), r1ok = (rg1 < n_nodes);
            for (int s = 0; s < KSTEPS_FULL + 1; s++) {
                const int k0 = s * 16;
                const bool kv0 = (k0 + q2     < IN_DIM);
                const bool kv1 = (k0 + q2 + 1 < IN_DIM);
                const bool kv2 = (k0 + q2 + 8 < IN_DIM);
                const bool kv3 = (k0 + q2 + 9 < IN_DIM);
                float f00 = (r0ok && kv0) ? __ldg(p0 + k0)     : 0.0f;
                float f01 = (r0ok && kv1) ? __ldg(p0 + k0 + 1) : 0.0f;
                float f02 = (r0ok && kv2) ? __ldg(p0 + k0 + 8) : 0.0f;
                float f03 = (r0ok && kv3) ? __ldg(p0 + k0 + 9) : 0.0f;
                float f10 = (r1ok && kv0) ? __ldg(p1 + k0)     : 0.0f;
                float f11 = (r1ok && kv1) ? __ldg(p1 + k0 + 1) : 0.0f;
                float f12 = (r1ok && kv2) ? __ldg(p1 + k0 + 8) : 0.0f;
                float f13 = (r1ok && kv3) ? __ldg(p1 + k0 + 9) : 0.0f;
                uint32_t a0h, a0l, a1h, a1l, a2h, a2l, a3h, a3l;
                split2(f00, f01, a0h, a0l);
                split2(f02, f03, a2h, a2l);
                split2(f10, f11, a1h, a1l);
                split2(f12, f13, a3h, a3l);
                const int kw = k0 >> 1;
                #pragma unroll
                for (int h = 0; h < 2; h++) {
                    const int base = (h ? bw1 : bw0) + kw;
                    const uint32_t b0h = shi[base], b1h = shi[base + 4];
                    const uint32_t b0l = slo[base], b1l = slo[base + 4];
                    mma16816(d[h][0], d[h][1], d[h][2], d[h][3],
                             a0h, a1h, a2h, a3h, b0h, b1h);
                    mma16816(d[h][0], d[h][1], d[h][2], d[h][3],
                             a0h, a1h, a2h, a3h, b0l, b1l);
                    mma16816(d[h][0], d[h][1], d[h][2], d[h][3],
                             a0l, a1l, a2l, a3l, b0h, b1h);
                }
            }
        }

        if (rg0 < n_nodes) {
            float* o = g_xw1 + (size_t)rg0 * HID;
            *(float2*)(o + q2)     = make_float2(d[0][0], d[0][1]);
            *(float2*)(o + 8 + q2) = make_float2(d[1][0], d[1][1]);
        }
        if (rg1 < n_nodes) {
            float* o = g_xw1 + (size_t)rg1 * HID;
            *(float2*)(o + q2)     = make_float2(d[0][2], d[0][3]);
            *(float2*)(o + 8 + q2) = make_float2(d[1][2], d[1][3]);
        }
    }
}

// ---------------------------------------------------------------------------
__global__ __launch_bounds__(256) void spmm1_gather_kernel(int n_nodes)
{
    const int warp_id = (blockIdx.x * blockDim.x + threadIdx.x) >> 5;
    if (warp_id >= n_nodes) return;
    const int lane = threadIdx.x & 31;
    const int g  = lane >> 2;
    const int j4 = lane & 3;

    const int start = g_rowptr[warp_id];
    const int end   = g_rowptr[warp_id + 1];

    float4 acc = make_float4(0.f, 0.f, 0.f, 0.f);
    for (int e = start + g; e < end; e += 8) {
        const int2 ev = __ldg(&g_csr[e]);
        const float v = __int_as_float(ev.y);
        const float4 x = __ldg((const float4*)(g_xw1 + (size_t)ev.x * HID) + j4);
        acc.x += v * x.x; acc.y += v * x.y; acc.z += v * x.z; acc.w += v * x.w;
    }
    #pragma unroll
    for (int off = 16; off >= 4; off >>= 1) {
        acc.x += __shfl_xor_sync(0xffffffffu, acc.x, off);
        acc.y += __shfl_xor_sync(0xffffffffu, acc.y, off);
        acc.z += __shfl_xor_sync(0xffffffffu, acc.z, off);
        acc.w += __shfl_xor_sync(0xffffffffu, acc.w, off);
    }
    if (g == 0)
        ((float4*)(g_h + (size_t)warp_id * HID))[j4] = acc;
}

// ---------------------------------------------------------------------------
__global__ __launch_bounds__(256) void gemm2_kernel(
    const float* __restrict__ b1,
    const float* __restrict__ W2,
    int n_nodes)
{
    __shared__ float sW2[HID * OUTD];
    __shared__ float sb1[HID];
    if (threadIdx.x < HID * OUTD) sW2[threadIdx.x] = W2[threadIdx.x];
    if (threadIdx.x < HID)        sb1[threadIdx.x] = b1[threadIdx.x];
    __syncthreads();

    int i = blockIdx.x * blockDim.x + threadIdx.x;
    if (i >= n_nodes) return;

    float h[HID];
    const float4* hp = (const float4*)(g_h + (size_t)i * HID);
    #pragma unroll
    for (int q = 0; q < 4; q++) {
        float4 a = hp[q];
        h[4 * q + 0] = a.x; h[4 * q + 1] = a.y;
        h[4 * q + 2] = a.z; h[4 * q + 3] = a.w;
    }

    float o[OUTD];
    #pragma unroll
    for (int j = 0; j < OUTD; j++) o[j] = 0.0f;
    #pragma unroll
    for (int k = 0; k < HID; k++) {
        const float hv = fmaxf(h[k] + sb1[k], 0.0f);
        #pragma unroll
        for (int j = 0; j < OUTD; j++) o[j] += hv * sW2[k * OUTD + j];
    }

    float4* gp = (float4*)(g_g + (size_t)i * 8);
    gp[0] = make_float4(o[0], o[1], o[2], o[3]);
    gp[1] = make_float4(o[4], o[5], o[6], 0.0f);
}

// ---------------------------------------------------------------------------
__global__ __launch_bounds__(256) void spmm2_gather_kernel(
    float* __restrict__ out, const float* __restrict__ b2, int n_nodes)
{
    const int warp_id = (blockIdx.x * blockDim.x + threadIdx.x) >> 5;
    if (warp_id >= n_nodes) return;
    const int lane = threadIdx.x & 31;
    const int g  = lane >> 1;
    const int j4 = lane & 1;

    const int start = g_rowptr[warp_id];
    const int end   = g_rowptr[warp_id + 1];

    float4 acc = make_float4(0.f, 0.f, 0.f, 0.f);
    for (int e = start + g; e < end; e += 16) {
        const int2 ev = __ldg(&g_csr[e]);
        const float v = __int_as_float(ev.y);
        const float4 x = __ldg((const float4*)(g_g + (size_t)ev.x * 8) + j4);
        acc.x += v * x.x; acc.y += v * x.y; acc.z += v * x.z; acc.w += v * x.w;
    }
    #pragma unroll
    for (int off = 16; off >= 2; off >>= 1) {
        acc.x += __shfl_xor_sync(0xffffffffu, acc.x, off);
        acc.y += __shfl_xor_sync(0xffffffffu, acc.y, off);
        acc.z += __shfl_xor_sync(0xffffffffu, acc.z, off);
        acc.w += __shfl_xor_sync(0xffffffffu, acc.w, off);
    }
    float* o = out + (size_t)warp_id * OUTD;
    if (lane == 0) {
        o[0] = acc.x + __ldg(b2 + 0);
        o[1] = acc.y + __ldg(b2 + 1);
        o[2] = acc.z + __ldg(b2 + 2);
        o[3] = acc.w + __ldg(b2 + 3);
    } else if (lane == 1) {
        o[4] = acc.x + __ldg(b2 + 4);
        o[5] = acc.y + __ldg(b2 + 5);
        o[6] = acc.z + __ldg(b2 + 6);
    }
}

// ---------------------------------------------------------------------------
extern "C" void kernel_launch(void* const* d_in, const int* in_sizes, int n_in,
                              void* d_out, int out_size)
{
    const void*  adj     = d_in[0];
    const float* vals    = (const float*)d_in[1];
    const float* feature = (const float*)d_in[2];
    const float* W1      = (const float*)d_in[3];
    const float* b1      = (const float*)d_in[4];
    const float* W2      = (const float*)d_in[5];
    const float* b2      = (const float*)d_in[6];
    float*       out     = (float*)d_out;

    const int n_edges   = in_sizes[1];
    const int n_nodes   = in_sizes[2] / IN_DIM;
    const int ntiles256 = (n_nodes + 255) / 256;
    const int nb        = (n_nodes + 1023) / 1024;

    static cudaStream_t s2 = nullptr;
    static cudaEvent_t ev_fork = nullptr, ev_join = nullptr;
    static int n_sms = 148;
    if (!s2) {
        cudaFuncSetAttribute(gemm1_mma_kernel,
                             cudaFuncAttributeMaxDynamicSharedMemorySize, SMEM_B_BYTES);
        cudaStreamCreateWithFlags(&s2, cudaStreamNonBlocking);
        cudaEventCreateWithFlags(&ev_fork, cudaEventDisableTiming);
        cudaEventCreateWithFlags(&ev_join, cudaEventDisableTiming);
        int dev = 0;
        cudaGetDevice(&dev);
        cudaDeviceGetAttribute(&n_sms, cudaDevAttrMultiProcessorCount, dev);
    }

    cudaEventRecord(ev_fork, 0);
    cudaStreamWaitEvent(s2, ev_fork, 0);

    // CSR chain on side stream; gemm1 stays the 4th launch (profiled slot).
    detect_idx_kernel<<<1, 1024, 0, s2>>>((const unsigned int*)adj, n_edges);
    zero_counts_kernel<<<nb, 1024, 0, s2>>>(n_nodes);
    histogram_kernel<<<(n_edges + 255) / 256, 256, 0, s2>>>(adj, n_edges);

    gemm1_mma_kernel<<<2 * n_sms, 512, SMEM_B_BYTES>>>(feature, W1, n_nodes, ntiles256);

    scan1_kernel<<<nb, 1024, 0, s2>>>(n_nodes);
    scan2_kernel<<<1, 256, 0, s2>>>(nb);
    scan3_kernel<<<nb, 1024, 0, s2>>>(n_nodes);
    scatter_kernel<<<(n_edges + 255) / 256, 256, 0, s2>>>(adj, vals, n_edges);
    cudaEventRecord(ev_join, s2);

    cudaStreamWaitEvent(0, ev_join, 0);
    spmm1_gather_kernel<<<(n_nodes * 32 + 255) / 256, 256>>>(n_nodes);
    gemm2_kernel<<<(n_nodes + 255) / 256, 256>>>(b1, W2, n_nodes);
    spmm2_gather_kernel<<<(n_nodes * 32 + 255) / 256, 256>>>(out, b2, n_nodes);
}

// round 11
// speedup vs baseline: 1.0313x; 1.0313x over previous
#include <cuda_runtime.h>
#include <cstdint>

#define IN_DIM 1433
#define HID 16
#define OUTD 7
#define MAXN 200000
#define MAXE 6400000
#define MAXNB 256

// gemm1 mma.sync tiling
#define KP 1448                  // B smem pitch (bf16) -> 724 words, conflict-free
#define KPW (KP / 2)
#define SMEM_BHALF (16 * KP * 2)             // 46336
#define SMEM_B_BYTES (2 * SMEM_BHALF)        // 92672
#define NCHUNK 45                             // 45*32 = 1440 >= 1433
#define CHUNKK 32
#define APITCH 36                             // fp32 pitch: (4*row+col)%32 conflict-free STS
#define ABUF_FLOATS (256 * APITCH)            // one buffer
#define SMEM_A_BYTES (2 * ABUF_FLOATS * 4)    // 73728
#define SMEM_TOTAL (SMEM_B_BYTES + SMEM_A_BYTES)   // 166400

// Scratch (__device__ globals; allocations are forbidden)
__device__ float g_xw1[(size_t)MAXN * HID];
__device__ float g_h[(size_t)MAXN * HID];
__device__ float g_g[(size_t)MAXN * 8];
__device__ int2  g_csr[(size_t)MAXE];
__device__ int   g_rowcnt[MAXN];
__device__ int   g_rowfill[MAXN];
__device__ int   g_rowptr[MAXN + 1];
__device__ int   g_blocksum[MAXNB];
__device__ int   g_blockoff[MAXNB];
__device__ int   g_idx64;

// ---------------------------------------------------------------------------
__device__ __forceinline__ void split2(float x0, float x1, uint32_t& hi, uint32_t& lo)
{
    uint32_t u0 = __float_as_uint(x0) & 0xFFFF0000u;
    uint32_t u1 = __float_as_uint(x1) & 0xFFFF0000u;
    hi = __byte_perm(u0, u1, 0x7632);
    float l0 = x0 - __uint_as_float(u0);
    float l1 = x1 - __uint_as_float(u1);
    asm("cvt.rn.bf16x2.f32 %0, %1, %2;" : "=r"(lo) : "f"(l1), "f"(l0));
}

__device__ __forceinline__ void mma16816(float& d0, float& d1, float& d2, float& d3,
                                         uint32_t a0, uint32_t a1, uint32_t a2, uint32_t a3,
                                         uint32_t b0, uint32_t b1)
{
    asm volatile(
        "mma.sync.aligned.m16n8k16.row.col.f32.bf16.bf16.f32 "
        "{%0,%1,%2,%3}, {%4,%5,%6,%7}, {%8,%9}, {%0,%1,%2,%3};"
        : "+f"(d0), "+f"(d1), "+f"(d2), "+f"(d3)
        : "r"(a0), "r"(a1), "r"(a2), "r"(a3), "r"(b0), "r"(b1));
}

// ---------------------------------------------------------------------------
__global__ void detect_idx_kernel(const unsigned int* __restrict__ adj_words, int n_edges)
{
    int i = threadIdx.x;
    int samples = n_edges < 1024 ? n_edges : 1024;
    int ok = 1;
    if (i < samples) ok = (adj_words[2 * i + 1] == 0u) ? 1 : 0;
    int all = __syncthreads_and(ok);
    if (i == 0) g_idx64 = all;
}

__device__ __forceinline__ int load_row(const void* adj, int e, int is64) {
    return is64 ? (int)__ldg((const long long*)adj + e)
                : __ldg((const int*)adj + e);
}
__device__ __forceinline__ int load_col(const void* adj, int e, int n_edges, int is64) {
    return is64 ? (int)__ldg((const long long*)adj + (size_t)n_edges + e)
                : __ldg((const int*)adj + (size_t)n_edges + e);
}

// ---------------------------------------------------------------------------
__global__ void zero_counts_kernel(int n)
{
    int i = blockIdx.x * blockDim.x + threadIdx.x;
    if (i < n) { g_rowcnt[i] = 0; g_rowfill[i] = 0; }
}

__global__ __launch_bounds__(256) void histogram_kernel(
    const void* __restrict__ adj, int n_edges)
{
    int e = blockIdx.x * blockDim.x + threadIdx.x;
    if (e >= n_edges) return;
    int r = load_row(adj, e, g_idx64);
    atomicAdd(&g_rowcnt[r], 1);
}

__device__ __forceinline__ int block_excl_scan(int v, int* warp_sums, int nwarps)
{
    const int lane = threadIdx.x & 31, w = threadIdx.x >> 5;
    int x = v;
    #pragma unroll
    for (int off = 1; off < 32; off <<= 1) {
        int y = __shfl_up_sync(0xffffffffu, x, off);
        if (lane >= off) x += y;
    }
    if (lane == 31) warp_sums[w] = x;
    __syncthreads();
    if (w == 0) {
        int s = (lane < nwarps) ? warp_sums[lane] : 0;
        #pragma unroll
        for (int off = 1; off < 32; off <<= 1) {
            int y = __shfl_up_sync(0xffffffffu, s, off);
            if (lane >= off) s += y;
        }
        if (lane < nwarps) warp_sums[lane] = s;
    }
    __syncthreads();
    int base = (w > 0) ? warp_sums[w - 1] : 0;
    return base + x - v;
}

__global__ __launch_bounds__(1024) void scan1_kernel(int n)
{
    __shared__ int ws[32];
    int i = blockIdx.x * 1024 + threadIdx.x;
    int v = (i < n) ? g_rowcnt[i] : 0;
    int ex = block_excl_scan(v, ws, 32);
    if (threadIdx.x == 1023) g_blocksum[blockIdx.x] = ex + v;
}

__global__ __launch_bounds__(256) void scan2_kernel(int nb)
{
    __shared__ int ws[32];
    int i = threadIdx.x;
    int v = (i < nb) ? g_blocksum[i] : 0;
    int ex = block_excl_scan(v, ws, 8);
    if (i < nb) g_blockoff[i] = ex;
}

__global__ __launch_bounds__(1024) void scan3_kernel(int n)
{
    __shared__ int ws[32];
    int i = blockIdx.x * 1024 + threadIdx.x;
    int v = (i < n) ? g_rowcnt[i] : 0;
    int ex = block_excl_scan(v, ws, 32);
    int base = g_blockoff[blockIdx.x];
    if (i < n)      g_rowptr[i] = base + ex;
    if (i == n - 1) g_rowptr[n] = base + ex + v;
}

__global__ __launch_bounds__(256) void scatter_kernel(
    const void* __restrict__ adj, const float* __restrict__ vals, int n_edges)
{
    int e = blockIdx.x * blockDim.x + threadIdx.x;
    if (e >= n_edges) return;
    const int is64 = g_idx64;
    int r = load_row(adj, e, is64);
    int c = load_col(adj, e, n_edges, is64);
    float v = __ldg(vals + e);
    int pos = g_rowptr[r] + atomicAdd(&g_rowfill[r], 1);
    g_csr[pos] = make_int2(c, __float_as_int(v));
}

// ---------------------------------------------------------------------------
// GEMM1 via mma.sync bf16 split (hh + hl + lh), A staged through smem:
// row-contiguous gmem loads (1-2 L1tex wavefronts/instr), double-buffered
// padded tile, fragments via conflict-light LDS.64. One sync per k-chunk.
__global__ __launch_bounds__(512) void gemm1_mma_kernel(
    const float* __restrict__ feature,
    const float* __restrict__ W1,
    int n_nodes, int ntiles256)
{
    extern __shared__ char smem[];
    uint32_t* shi = (uint32_t*)smem;
    uint32_t* slo = (uint32_t*)(smem + SMEM_BHALF);
    float*    sA  = (float*)(smem + SMEM_B_BYTES);   // [2][256][APITCH]

    const int tid  = threadIdx.x;
    const int warp = tid >> 5;
    const int lane = tid & 31;
    const int g    = lane >> 2;
    const int q2   = (lane & 3) * 2;

    // stage W1^T split (zero-padded to KP)
    for (int idx = tid; idx < 16 * KPW; idx += 512) {
        int n  = idx / KPW;
        int kp = idx - n * KPW;
        int k  = kp * 2;
        float w0 = (k     < IN_DIM) ? __ldg(W1 + (size_t)k       * HID + n) : 0.0f;
        float w1 = (k + 1 < IN_DIM) ? __ldg(W1 + (size_t)(k + 1) * HID + n) : 0.0f;
        uint32_t hi, lo;
        split2(w0, w1, hi, lo);
        shi[n * KPW + kp] = hi;
        slo[n * KPW + kp] = lo;
    }
    __syncthreads();

    const int bw0 = g * KPW + (lane & 3);
    const int bw1 = (8 + g) * KPW + (lane & 3);
    const int srow0 = warp * 16 + g;             // tile-local fragment rows
    const int sbase = warp * 16;                 // staging row base for this warp

    for (int t = blockIdx.x; t < ntiles256; t += gridDim.x) {
        const int row0 = t * 256;

        float d[2][4];
        #pragma unroll
        for (int h = 0; h < 2; h++)
            #pragma unroll
            for (int j = 0; j < 4; j++) d[h][j] = 0.0f;

        float st[16];
        // stage chunk 0
        #pragma unroll
        for (int i = 0; i < 16; i++) {
            const int r = row0 + sbase + i;
            const int k = lane;
            st[i] = (r < n_nodes) ? __ldg(feature + (size_t)r * IN_DIM + k) : 0.0f;
        }
        #pragma unroll
        for (int i = 0; i < 16; i++)
            sA[(sbase + i) * APITCH + lane] = st[i];
        __syncthreads();

        #pragma unroll 1
        for (int c = 0; c < NCHUNK; c++) {
            // prefetch chunk c+1 to registers (row-contiguous, coalesced)
            if (c + 1 < NCHUNK) {
                const int kc = (c + 1) * CHUNKK;
                const int k  = kc + lane;
                const bool kok = (k < IN_DIM);
                #pragma unroll
                for (int i = 0; i < 16; i++) {
                    const int r = row0 + sbase + i;
                    st[i] = (kok && r < n_nodes)
                          ? __ldg(feature + (size_t)r * IN_DIM + k) : 0.0f;
                }
            }

            // compute 2 k-steps from buffer c&1
            const float* buf = sA + (c & 1) * ABUF_FLOATS;
            #pragma unroll
            for (int ks = 0; ks < 2; ks++) {
                const int kk = ks * 16;
                const float2 v0 = *(const float2*)(buf + srow0 * APITCH + kk + q2);
                const float2 v2 = *(const float2*)(buf + srow0 * APITCH + kk + q2 + 8);
                const float2 v1 = *(const float2*)(buf + (srow0 + 8) * APITCH + kk + q2);
                const float2 v3 = *(const float2*)(buf + (srow0 + 8) * APITCH + kk + q2 + 8);

                uint32_t a0h, a0l, a1h, a1l, a2h, a2l, a3h, a3l;
                split2(v0.x, v0.y, a0h, a0l);
                split2(v2.x, v2.y, a2h, a2l);
                split2(v1.x, v1.y, a1h, a1l);
                split2(v3.x, v3.y, a3h, a3l);

                const int kw = c * (CHUNKK / 2) + ks * 8;
                #pragma unroll
                for (int h = 0; h < 2; h++) {
                    const int base = (h ? bw1 : bw0) + kw;
                    const uint32_t b0h = shi[base], b1h = shi[base + 4];
                    const uint32_t b0l = slo[base], b1l = slo[base + 4];
                    mma16816(d[h][0], d[h][1], d[h][2], d[h][3],
                             a0h, a1h, a2h, a3h, b0h, b1h);
                    mma16816(d[h][0], d[h][1], d[h][2], d[h][3],
                             a0h, a1h, a2h, a3h, b0l, b1l);
                    mma16816(d[h][0], d[h][1], d[h][2], d[h][3],
                             a0l, a1l, a2l, a3l, b0h, b1h);
                }
            }

            // store prefetched chunk into the other buffer; one sync per chunk
            if (c + 1 < NCHUNK) {
                float* nbuf = sA + ((c + 1) & 1) * ABUF_FLOATS;
                #pragma unroll
                for (int i = 0; i < 16; i++)
                    nbuf[(sbase + i) * APITCH + lane] = st[i];
                __syncthreads();
            }
        }

        // store D
        const int rg0 = row0 + srow0;
        const int rg1 = rg0 + 8;
        if (rg0 < n_nodes) {
            float* o = g_xw1 + (size_t)rg0 * HID;
            *(float2*)(o + q2)     = make_float2(d[0][0], d[0][1]);
            *(float2*)(o + 8 + q2) = make_float2(d[1][0], d[1][1]);
        }
        if (rg1 < n_nodes) {
            float* o = g_xw1 + (size_t)rg1 * HID;
            *(float2*)(o + q2)     = make_float2(d[0][2], d[0][3]);
            *(float2*)(o + 8 + q2) = make_float2(d[1][2], d[1][3]);
        }
        __syncthreads();   // tile done before re-staging chunk 0 of next tile
    }
}

// ---------------------------------------------------------------------------
__global__ __launch_bounds__(256) void spmm1_gather_kernel(int n_nodes)
{
    const int warp_id = (blockIdx.x * blockDim.x + threadIdx.x) >> 5;
    if (warp_id >= n_nodes) return;
    const int lane = threadIdx.x & 31;
    const int g  = lane >> 2;
    const int j4 = lane & 3;

    const int start = g_rowptr[warp_id];
    const int end   = g_rowptr[warp_id + 1];

    float4 acc = make_float4(0.f, 0.f, 0.f, 0.f);
    for (int e = start + g; e < end; e += 8) {
        const int2 ev = __ldg(&g_csr[e]);
        const float v = __int_as_float(ev.y);
        const float4 x = __ldg((const float4*)(g_xw1 + (size_t)ev.x * HID) + j4);
        acc.x += v * x.x; acc.y += v * x.y; acc.z += v * x.z; acc.w += v * x.w;
    }
    #pragma unroll
    for (int off = 16; off >= 4; off >>= 1) {
        acc.x += __shfl_xor_sync(0xffffffffu, acc.x, off);
        acc.y += __shfl_xor_sync(0xffffffffu, acc.y, off);
        acc.z += __shfl_xor_sync(0xffffffffu, acc.z, off);
        acc.w += __shfl_xor_sync(0xffffffffu, acc.w, off);
    }
    if (g == 0)
        ((float4*)(g_h + (size_t)warp_id * HID))[j4] = acc;
}

// ---------------------------------------------------------------------------
__global__ __launch_bounds__(256) void gemm2_kernel(
    const float* __restrict__ b1,
    const float* __restrict__ W2,
    int n_nodes)
{
    __shared__ float sW2[HID * OUTD];
    __shared__ float sb1[HID];
    if (threadIdx.x < HID * OUTD) sW2[threadIdx.x] = W2[threadIdx.x];
    if (threadIdx.x < HID)        sb1[threadIdx.x] = b1[threadIdx.x];
    __syncthreads();

    int i = blockIdx.x * blockDim.x + threadIdx.x;
    if (i >= n_nodes) return;

    float h[HID];
    const float4* hp = (const float4*)(g_h + (size_t)i * HID);
    #pragma unroll
    for (int q = 0; q < 4; q++) {
        float4 a = hp[q];
        h[4 * q + 0] = a.x; h[4 * q + 1] = a.y;
        h[4 * q + 2] = a.z; h[4 * q + 3] = a.w;
    }

    float o[OUTD];
    #pragma unroll
    for (int j = 0; j < OUTD; j++) o[j] = 0.0f;
    #pragma unroll
    for (int k = 0; k < HID; k++) {
        const float hv = fmaxf(h[k] + sb1[k], 0.0f);
        #pragma unroll
        for (int j = 0; j < OUTD; j++) o[j] += hv * sW2[k * OUTD + j];
    }

    float4* gp = (float4*)(g_g + (size_t)i * 8);
    gp[0] = make_float4(o[0], o[1], o[2], o[3]);
    gp[1] = make_float4(o[4], o[5], o[6], 0.0f);
}

// ---------------------------------------------------------------------------
__global__ __launch_bounds__(256) void spmm2_gather_kernel(
    float* __restrict__ out, const float* __restrict__ b2, int n_nodes)
{
    const int warp_id = (blockIdx.x * blockDim.x + threadIdx.x) >> 5;
    if (warp_id >= n_nodes) return;
    const int lane = threadIdx.x & 31;
    const int g  = lane >> 1;
    const int j4 = lane & 1;

    const int start = g_rowptr[warp_id];
    const int end   = g_rowptr[warp_id + 1];

    float4 acc = make_float4(0.f, 0.f, 0.f, 0.f);
    for (int e = start + g; e < end; e += 16) {
        const int2 ev = __ldg(&g_csr[e]);
        const float v = __int_as_float(ev.y);
        const float4 x = __ldg((const float4*)(g_g + (size_t)ev.x * 8) + j4);
        acc.x += v * x.x; acc.y += v * x.y; acc.z += v * x.z; acc.w += v * x.w;
    }
    #pragma unroll
    for (int off = 16; off >= 2; off >>= 1) {
        acc.x += __shfl_xor_sync(0xffffffffu, acc.x, off);
        acc.y += __shfl_xor_sync(0xffffffffu, acc.y, off);
        acc.z += __shfl_xor_sync(0xffffffffu, acc.z, off);
        acc.w += __shfl_xor_sync(0xffffffffu, acc.w, off);
    }
    float* o = out + (size_t)warp_id * OUTD;
    if (lane == 0) {
        o[0] = acc.x + __ldg(b2 + 0);
        o[1] = acc.y + __ldg(b2 + 1);
        o[2] = acc.z + __ldg(b2 + 2);
        o[3] = acc.w + __ldg(b2 + 3);
    } else if (lane == 1) {
        o[4] = acc.x + __ldg(b2 + 4);
        o[5] = acc.y + __ldg(b2 + 5);
        o[6] = acc.z + __ldg(b2 + 6);
    }
}

// ---------------------------------------------------------------------------
extern "C" void kernel_launch(void* const* d_in, const int* in_sizes, int n_in,
                              void* d_out, int out_size)
{
    const void*  adj     = d_in[0];
    const float* vals    = (const float*)d_in[1];
    const float* feature = (const float*)d_in[2];
    const float* W1      = (const float*)d_in[3];
    const float* b1      = (const float*)d_in[4];
    const float* W2      = (const float*)d_in[5];
    const float* b2      = (const float*)d_in[6];
    float*       out     = (float*)d_out;

    const int n_edges   = in_sizes[1];
    const int n_nodes   = in_sizes[2] / IN_DIM;
    const int ntiles256 = (n_nodes + 255) / 256;
    const int nb        = (n_nodes + 1023) / 1024;

    static cudaStream_t s2 = nullptr;
    static cudaEvent_t ev_fork = nullptr, ev_join = nullptr;
    static int n_sms = 148;
    if (!s2) {
        cudaFuncSetAttribute(gemm1_mma_kernel,
                             cudaFuncAttributeMaxDynamicSharedMemorySize, SMEM_TOTAL);
        cudaStreamCreateWithFlags(&s2, cudaStreamNonBlocking);
        cudaEventCreateWithFlags(&ev_fork, cudaEventDisableTiming);
        cudaEventCreateWithFlags(&ev_join, cudaEventDisableTiming);
        int dev = 0;
        cudaGetDevice(&dev);
        cudaDeviceGetAttribute(&n_sms, cudaDevAttrMultiProcessorCount, dev);
    }

    cudaEventRecord(ev_fork, 0);
    cudaStreamWaitEvent(s2, ev_fork, 0);

    // CSR chain on side stream; gemm1 stays the 4th launch (profiled slot).
    detect_idx_kernel<<<1, 1024, 0, s2>>>((const unsigned int*)adj, n_edges);
    zero_counts_kernel<<<nb, 1024, 0, s2>>>(n_nodes);
    histogram_kernel<<<(n_edges + 255) / 256, 256, 0, s2>>>(adj, n_edges);

    gemm1_mma_kernel<<<n_sms, 512, SMEM_TOTAL>>>(feature, W1, n_nodes, ntiles256);

    scan1_kernel<<<nb, 1024, 0, s2>>>(n_nodes);
    scan2_kernel<<<1, 256, 0, s2>>>(nb);
    scan3_kernel<<<nb, 1024, 0, s2>>>(n_nodes);
    scatter_kernel<<<(n_edges + 255) / 256, 256, 0, s2>>>(adj, vals, n_edges);
    cudaEventRecord(ev_join, s2);

    cudaStreamWaitEvent(0, ev_join, 0);
    spmm1_gather_kernel<<<(n_nodes * 32 + 255) / 256, 256>>>(n_nodes);
    gemm2_kernel<<<(n_nodes + 255) / 256, 256>>>(b1, W2, n_nodes);
    spmm2_gather_kernel<<<(n_nodes * 32 + 255) / 256, 256>>>(out, b2, n_nodes);
}

// round 12
// speedup vs baseline: 1.0349x; 1.0035x over previous
#include <cuda_runtime.h>
#include <cstdint>

#define IN_DIM 1433
#define HID 16
#define OUTD 7
#define MAXN 200000
#define MAXE 6400000
#define MAXNB 256

// gemm1 mma.sync tiling
#define KP 1448                  // B smem pitch (bf16) -> 724 words, conflict-free
#define KPW (KP / 2)
#define SMEM_BHALF (16 * KP * 2)             // 46336
#define SMEM_B_BYTES (2 * SMEM_BHALF)        // 92672
#define NCHUNK 45                             // 45*32 = 1440 >= 1433
#define CHUNKK 32
#define APITCH 36                             // fp32 pitch: (4r+c)%32 conflict-free
#define ABUF_FLOATS (256 * APITCH)
#define SMEM_A_BYTES (2 * ABUF_FLOATS * 4)    // 73728
#define SMEM_TOTAL (SMEM_B_BYTES + SMEM_A_BYTES)   // 166400

// Scratch (__device__ globals; allocations are forbidden)
__device__ float g_xw1[(size_t)MAXN * HID];
__device__ float g_h[(size_t)MAXN * HID];
__device__ float g_g[(size_t)MAXN * 8];
__device__ int2  g_csr[(size_t)MAXE];
__device__ int   g_rowcnt[MAXN];
__device__ int   g_rowfill[MAXN];
__device__ int   g_rowptr[MAXN + 1];
__device__ int   g_blocksum[MAXNB];
__device__ int   g_blockoff[MAXNB];
__device__ int   g_idx64;

// ---------------------------------------------------------------------------
__device__ __forceinline__ void split2(float x0, float x1, uint32_t& hi, uint32_t& lo)
{
    uint32_t u0 = __float_as_uint(x0) & 0xFFFF0000u;
    uint32_t u1 = __float_as_uint(x1) & 0xFFFF0000u;
    hi = __byte_perm(u0, u1, 0x7632);
    float l0 = x0 - __uint_as_float(u0);
    float l1 = x1 - __uint_as_float(u1);
    asm("cvt.rn.bf16x2.f32 %0, %1, %2;" : "=r"(lo) : "f"(l1), "f"(l0));
}

__device__ __forceinline__ void mma16816(float& d0, float& d1, float& d2, float& d3,
                                         uint32_t a0, uint32_t a1, uint32_t a2, uint32_t a3,
                                         uint32_t b0, uint32_t b1)
{
    asm volatile(
        "mma.sync.aligned.m16n8k16.row.col.f32.bf16.bf16.f32 "
        "{%0,%1,%2,%3}, {%4,%5,%6,%7}, {%8,%9}, {%0,%1,%2,%3};"
        : "+f"(d0), "+f"(d1), "+f"(d2), "+f"(d3)
        : "r"(a0), "r"(a1), "r"(a2), "r"(a3), "r"(b0), "r"(b1));
}

// ---------------------------------------------------------------------------
__global__ void detect_idx_kernel(const unsigned int* __restrict__ adj_words, int n_edges)
{
    int i = threadIdx.x;
    int samples = n_edges < 1024 ? n_edges : 1024;
    int ok = 1;
    if (i < samples) ok = (adj_words[2 * i + 1] == 0u) ? 1 : 0;
    int all = __syncthreads_and(ok);
    if (i == 0) g_idx64 = all;
}

__device__ __forceinline__ int load_row(const void* adj, int e, int is64) {
    return is64 ? (int)__ldg((const long long*)adj + e)
                : __ldg((const int*)adj + e);
}
__device__ __forceinline__ int load_col(const void* adj, int e, int n_edges, int is64) {
    return is64 ? (int)__ldg((const long long*)adj + (size_t)n_edges + e)
                : __ldg((const int*)adj + (size_t)n_edges + e);
}

// ---------------------------------------------------------------------------
__global__ void zero_counts_kernel(int n)
{
    int i = blockIdx.x * blockDim.x + threadIdx.x;
    if (i < n) { g_rowcnt[i] = 0; g_rowfill[i] = 0; }
}

__global__ __launch_bounds__(256) void histogram_kernel(
    const void* __restrict__ adj, int n_edges)
{
    int e = blockIdx.x * blockDim.x + threadIdx.x;
    if (e >= n_edges) return;
    int r = load_row(adj, e, g_idx64);
    atomicAdd(&g_rowcnt[r], 1);
}

__device__ __forceinline__ int block_excl_scan(int v, int* warp_sums, int nwarps)
{
    const int lane = threadIdx.x & 31, w = threadIdx.x >> 5;
    int x = v;
    #pragma unroll
    for (int off = 1; off < 32; off <<= 1) {
        int y = __shfl_up_sync(0xffffffffu, x, off);
        if (lane >= off) x += y;
    }
    if (lane == 31) warp_sums[w] = x;
    __syncthreads();
    if (w == 0) {
        int s = (lane < nwarps) ? warp_sums[lane] : 0;
        #pragma unroll
        for (int off = 1; off < 32; off <<= 1) {
            int y = __shfl_up_sync(0xffffffffu, s, off);
            if (lane >= off) s += y;
        }
        if (lane < nwarps) warp_sums[lane] = s;
    }
    __syncthreads();
    int base = (w > 0) ? warp_sums[w - 1] : 0;
    return base + x - v;
}

__global__ __launch_bounds__(1024) void scan1_kernel(int n)
{
    __shared__ int ws[32];
    int i = blockIdx.x * 1024 + threadIdx.x;
    int v = (i < n) ? g_rowcnt[i] : 0;
    int ex = block_excl_scan(v, ws, 32);
    if (threadIdx.x == 1023) g_blocksum[blockIdx.x] = ex + v;
}

__global__ __launch_bounds__(256) void scan2_kernel(int nb)
{
    __shared__ int ws[32];
    int i = threadIdx.x;
    int v = (i < nb) ? g_blocksum[i] : 0;
    int ex = block_excl_scan(v, ws, 8);
    if (i < nb) g_blockoff[i] = ex;
}

__global__ __launch_bounds__(1024) void scan3_kernel(int n)
{
    __shared__ int ws[32];
    int i = blockIdx.x * 1024 + threadIdx.x;
    int v = (i < n) ? g_rowcnt[i] : 0;
    int ex = block_excl_scan(v, ws, 32);
    int base = g_blockoff[blockIdx.x];
    if (i < n)      g_rowptr[i] = base + ex;
    if (i == n - 1) g_rowptr[n] = base + ex + v;
}

__global__ __launch_bounds__(256) void scatter_kernel(
    const void* __restrict__ adj, const float* __restrict__ vals, int n_edges)
{
    int e = blockIdx.x * blockDim.x + threadIdx.x;
    if (e >= n_edges) return;
    const int is64 = g_idx64;
    int r = load_row(adj, e, is64);
    int c = load_col(adj, e, n_edges, is64);
    float v = __ldg(vals + e);
    int pos = g_rowptr[r] + atomicAdd(&g_rowfill[r], 1);
    g_csr[pos] = make_int2(c, __float_as_int(v));
}

// ---------------------------------------------------------------------------
// GEMM1 via mma.sync bf16 split (hh + hl + lh).
// 1024 threads = 32 warps: warps w and w+16 share the same 16 A-rows and each
// computes one n8 half (3 MMAs/k-step). A double-buffered in smem with one
// __syncthreads per 32-k chunk: sync -> LDG next -> compute -> STS next.
__global__ __launch_bounds__(1024) void gemm1_mma_kernel(
    const float* __restrict__ feature,
    const float* __restrict__ W1,
    int n_nodes, int ntiles256)
{
    extern __shared__ char smem[];
    uint32_t* shi = (uint32_t*)smem;
    uint32_t* slo = (uint32_t*)(smem + SMEM_BHALF);
    float*    sA  = (float*)(smem + SMEM_B_BYTES);   // [2][256][APITCH]

    const int tid  = threadIdx.x;
    const int warp = tid >> 5;
    const int lane = tid & 31;
    const int g    = lane >> 2;
    const int q2   = (lane & 3) * 2;
    const int h    = warp >> 4;          // n8 half owned by this warp
    const int wrow = warp & 15;          // A row-group

    // stage W1^T split (zero-padded to KP)
    for (int idx = tid; idx < 16 * KPW; idx += 1024) {
        int n  = idx / KPW;
        int kp = idx - n * KPW;
        int k  = kp * 2;
        float w0 = (k     < IN_DIM) ? __ldg(W1 + (size_t)k       * HID + n) : 0.0f;
        float w1 = (k + 1 < IN_DIM) ? __ldg(W1 + (size_t)(k + 1) * HID + n) : 0.0f;
        uint32_t hi, lo;
        split2(w0, w1, hi, lo);
        shi[n * KPW + kp] = hi;
        slo[n * KPW + kp] = lo;
    }
    __syncthreads();

    const int bw    = (h * 8 + g) * KPW + (lane & 3);
    const int srow0 = wrow * 16 + g;

    // staging assignment: 8 elements/thread, idx = tid + i*1024
    // r = idx>>5 (0..255), col = idx&31  -> coalesced, conflict-free STS
    const int str = tid >> 5;            // base row stride pattern handled below

    for (int t = blockIdx.x; t < ntiles256; t += gridDim.x) {
        const int row0 = t * 256;

        float d0 = 0.f, d1 = 0.f, d2 = 0.f, d3 = 0.f;
        float st[8];

        // prologue: stage chunk 0
        #pragma unroll
        for (int i = 0; i < 8; i++) {
            const int idx = tid + i * 1024;
            const int r   = idx >> 5;
            const int col = idx & 31;
            const int gr  = row0 + r;
            st[i] = (gr < n_nodes && col < IN_DIM)
                  ? __ldg(feature + (size_t)gr * IN_DIM + col) : 0.0f;
        }
        #pragma unroll
        for (int i = 0; i < 8; i++) {
            const int idx = tid + i * 1024;
            sA[(idx >> 5) * APITCH + (idx & 31)] = st[i];
        }

        #pragma unroll 1
        for (int c = 0; c < NCHUNK; c++) {
            __syncthreads();   // publish chunk c; retire readers of chunk c-1

            // LDG chunk c+1 into registers (overlaps compute below)
            if (c + 1 < NCHUNK) {
                const int kc = (c + 1) * CHUNKK;
                #pragma unroll
                for (int i = 0; i < 8; i++) {
                    const int idx = tid + i * 1024;
                    const int r   = idx >> 5;
                    const int col = kc + (idx & 31);
                    const int gr  = row0 + r;
                    st[i] = (gr < n_nodes && col < IN_DIM)
                          ? __ldg(feature + (size_t)gr * IN_DIM + col) : 0.0f;
                }
            }

            // compute chunk c from buffer c&1
            const float* buf = sA + (c & 1) * ABUF_FLOATS;
            #pragma unroll
            for (int ks = 0; ks < 2; ks++) {
                const int kk = ks * 16;
                const float2 v0 = *(const float2*)(buf + srow0 * APITCH + kk + q2);
                const float2 v2 = *(const float2*)(buf + srow0 * APITCH + kk + q2 + 8);
                const float2 v1 = *(const float2*)(buf + (srow0 + 8) * APITCH + kk + q2);
                const float2 v3 = *(const float2*)(buf + (srow0 + 8) * APITCH + kk + q2 + 8);

                uint32_t a0h, a0l, a1h, a1l, a2h, a2l, a3h, a3l;
                split2(v0.x, v0.y, a0h, a0l);
                split2(v2.x, v2.y, a2h, a2l);
                split2(v1.x, v1.y, a1h, a1l);
                split2(v3.x, v3.y, a3h, a3l);

                const int base = bw + c * (CHUNKK / 2) + ks * 8;
                const uint32_t b0h = shi[base], b1h = shi[base + 4];
                const uint32_t b0l = slo[base], b1l = slo[base + 4];
                mma16816(d0, d1, d2, d3, a0h, a1h, a2h, a3h, b0h, b1h);
                mma16816(d0, d1, d2, d3, a0h, a1h, a2h, a3h, b0l, b1l);
                mma16816(d0, d1, d2, d3, a0l, a1l, a2l, a3l, b0h, b1h);
            }

            // STS chunk c+1 into the other buffer
            if (c + 1 < NCHUNK) {
                float* nbuf = sA + ((c + 1) & 1) * ABUF_FLOATS;
                #pragma unroll
                for (int i = 0; i < 8; i++) {
                    const int idx = tid + i * 1024;
                    nbuf[(idx >> 5) * APITCH + (idx & 31)] = st[i];
                }
            }
        }

        // store D (each warp owns an 8-col half of its 16 rows)
        const int rg0 = row0 + srow0;
        const int rg1 = rg0 + 8;
        if (rg0 < n_nodes)
            *(float2*)(g_xw1 + (size_t)rg0 * HID + h * 8 + q2) = make_float2(d0, d1);
        if (rg1 < n_nodes)
            *(float2*)(g_xw1 + (size_t)rg1 * HID + h * 8 + q2) = make_float2(d2, d3);

        __syncthreads();   // all reads of buffers done before next tile's prologue
    }
    (void)str;
}

// ---------------------------------------------------------------------------
__global__ __launch_bounds__(256) void spmm1_gather_kernel(int n_nodes)
{
    const int warp_id = (blockIdx.x * blockDim.x + threadIdx.x) >> 5;
    if (warp_id >= n_nodes) return;
    const int lane = threadIdx.x & 31;
    const int g  = lane >> 2;
    const int j4 = lane & 3;

    const int start = g_rowptr[warp_id];
    const int end   = g_rowptr[warp_id + 1];

    float4 acc = make_float4(0.f, 0.f, 0.f, 0.f);
    for (int e = start + g; e < end; e += 8) {
        const int2 ev = __ldg(&g_csr[e]);
        const float v = __int_as_float(ev.y);
        const float4 x = __ldg((const float4*)(g_xw1 + (size_t)ev.x * HID) + j4);
        acc.x += v * x.x; acc.y += v * x.y; acc.z += v * x.z; acc.w += v * x.w;
    }
    #pragma unroll
    for (int off = 16; off >= 4; off >>= 1) {
        acc.x += __shfl_xor_sync(0xffffffffu, acc.x, off);
        acc.y += __shfl_xor_sync(0xffffffffu, acc.y, off);
        acc.z += __shfl_xor_sync(0xffffffffu, acc.z, off);
        acc.w += __shfl_xor_sync(0xffffffffu, acc.w, off);
    }
    if (g == 0)
        ((float4*)(g_h + (size_t)warp_id * HID))[j4] = acc;
}

// ---------------------------------------------------------------------------
__global__ __launch_bounds__(256) void gemm2_kernel(
    const float* __restrict__ b1,
    const float* __restrict__ W2,
    int n_nodes)
{
    __shared__ float sW2[HID * OUTD];
    __shared__ float sb1[HID];
    if (threadIdx.x < HID * OUTD) sW2[threadIdx.x] = W2[threadIdx.x];
    if (threadIdx.x < HID)        sb1[threadIdx.x] = b1[threadIdx.x];
    __syncthreads();

    int i = blockIdx.x * blockDim.x + threadIdx.x;
    if (i >= n_nodes) return;

    float h[HID];
    const float4* hp = (const float4*)(g_h + (size_t)i * HID);
    #pragma unroll
    for (int q = 0; q < 4; q++) {
        float4 a = hp[q];
        h[4 * q + 0] = a.x; h[4 * q + 1] = a.y;
        h[4 * q + 2] = a.z; h[4 * q + 3] = a.w;
    }

    float o[OUTD];
    #pragma unroll
    for (int j = 0; j < OUTD; j++) o[j] = 0.0f;
    #pragma unroll
    for (int k = 0; k < HID; k++) {
        const float hv = fmaxf(h[k] + sb1[k], 0.0f);
        #pragma unroll
        for (int j = 0; j < OUTD; j++) o[j] += hv * sW2[k * OUTD + j];
    }

    float4* gp = (float4*)(g_g + (size_t)i * 8);
    gp[0] = make_float4(o[0], o[1], o[2], o[3]);
    gp[1] = make_float4(o[4], o[5], o[6], 0.0f);
}

// ---------------------------------------------------------------------------
__global__ __launch_bounds__(256) void spmm2_gather_kernel(
    float* __restrict__ out, const float* __restrict__ b2, int n_nodes)
{
    const int warp_id = (blockIdx.x * blockDim.x + threadIdx.x) >> 5;
    if (warp_id >= n_nodes) return;
    const int lane = threadIdx.x & 31;
    const int g  = lane >> 1;
    const int j4 = lane & 1;

    const int start = g_rowptr[warp_id];
    const int end   = g_rowptr[warp_id + 1];

    float4 acc = make_float4(0.f, 0.f, 0.f, 0.f);
    for (int e = start + g; e < end; e += 16) {
        const int2 ev = __ldg(&g_csr[e]);
        const float v = __int_as_float(ev.y);
        const float4 x = __ldg((const float4*)(g_g + (size_t)ev.x * 8) + j4);
        acc.x += v * x.x; acc.y += v * x.y; acc.z += v * x.z; acc.w += v * x.w;
    }
    #pragma unroll
    for (int off = 16; off >= 2; off >>= 1) {
        acc.x += __shfl_xor_sync(0xffffffffu, acc.x, off);
        acc.y += __shfl_xor_sync(0xffffffffu, acc.y, off);
        acc.z += __shfl_xor_sync(0xffffffffu, acc.z, off);
        acc.w += __shfl_xor_sync(0xffffffffu, acc.w, off);
    }
    float* o = out + (size_t)warp_id * OUTD;
    if (lane == 0) {
        o[0] = acc.x + __ldg(b2 + 0);
        o[1] = acc.y + __ldg(b2 + 1);
        o[2] = acc.z + __ldg(b2 + 2);
        o[3] = acc.w + __ldg(b2 + 3);
    } else if (lane == 1) {
        o[4] = acc.x + __ldg(b2 + 4);
        o[5] = acc.y + __ldg(b2 + 5);
        o[6] = acc.z + __ldg(b2 + 6);
    }
}

// ---------------------------------------------------------------------------
extern "C" void kernel_launch(void* const* d_in, const int* in_sizes, int n_in,
                              void* d_out, int out_size)
{
    const void*  adj     = d_in[0];
    const float* vals    = (const float*)d_in[1];
    const float* feature = (const float*)d_in[2];
    const float* W1      = (const float*)d_in[3];
    const float* b1      = (const float*)d_in[4];
    const float* W2      = (const float*)d_in[5];
    const float* b2      = (const float*)d_in[6];
    float*       out     = (float*)d_out;

    const int n_edges   = in_sizes[1];
    const int n_nodes   = in_sizes[2] / IN_DIM;
    const int ntiles256 = (n_nodes + 255) / 256;
    const int nb        = (n_nodes + 1023) / 1024;

    static cudaStream_t s2 = nullptr;
    static cudaEvent_t ev_fork = nullptr, ev_join = nullptr;
    static int n_sms = 148;
    if (!s2) {
        cudaFuncSetAttribute(gemm1_mma_kernel,
                             cudaFuncAttributeMaxDynamicSharedMemorySize, SMEM_TOTAL);
        cudaStreamCreateWithFlags(&s2, cudaStreamNonBlocking);
        cudaEventCreateWithFlags(&ev_fork, cudaEventDisableTiming);
        cudaEventCreateWithFlags(&ev_join, cudaEventDisableTiming);
        int dev = 0;
        cudaGetDevice(&dev);
        cudaDeviceGetAttribute(&n_sms, cudaDevAttrMultiProcessorCount, dev);
    }

    cudaEventRecord(ev_fork, 0);
    cudaStreamWaitEvent(s2, ev_fork, 0);

    // CSR chain on side stream; gemm1 stays the 4th launch (profiled slot).
    detect_idx_kernel<<<1, 1024, 0, s2>>>((const unsigned int*)adj, n_edges);
    zero_counts_kernel<<<nb, 1024, 0, s2>>>(n_nodes);
    histogram_kernel<<<(n_edges + 255) / 256, 256, 0, s2>>>(adj, n_edges);

    gemm1_mma_kernel<<<n_sms, 1024, SMEM_TOTAL>>>(feature, W1, n_nodes, ntiles256);

    scan1_kernel<<<nb, 1024, 0, s2>>>(n_nodes);
    scan2_kernel<<<1, 256, 0, s2>>>(nb);
    scan3_kernel<<<nb, 1024, 0, s2>>>(n_nodes);
    scatter_kernel<<<(n_edges + 255) / 256, 256, 0, s2>>>(adj, vals, n_edges);
    cudaEventRecord(ev_join, s2);

    cudaStreamWaitEvent(0, ev_join, 0);
    spmm1_gather_kernel<<<(n_nodes * 32 + 255) / 256, 256>>>(n_nodes);
    gemm2_kernel<<<(n_nodes + 255) / 256, 256>>>(b1, W2, n_nodes);
    spmm2_gather_kernel<<<(n_nodes * 32 + 255) / 256, 256>>>(out, b2, n_nodes);
}